// round 16
// baseline (speedup 1.0000x reference)
#include <cuda_runtime.h>
#include <cuda_bf16.h>
#include <cstdint>

#define NROWS 16384
#define DIM   256
#define NT    128
#define NTILES 8256                // NT*(NT+1)/2
#define NCTA  148
#define NTHR  512
#define LDSB  528                  // A: bytes per smem row (512 + 16 pad)
#define KSL2  (5.0f * 1.44269504088896f)        // kappa * log2e
#define A_BYTES  (128 * LDSB)                   // 67584
#define BH_BYTES (256 * 256)                    // 65536 per k-half buffer
#define SMEM_BYTES (A_BYTES + 2 * BH_BYTES)     // 198656

__device__ __nv_bfloat16 g_xn[NROWS * DIM];   // normalized rows, bf16
__device__ float         g_density[NROWS];

static __device__ __forceinline__ uint32_t pack_bf2(float a, float b) {
    __nv_bfloat162 h = __floats2bfloat162_rn(a, b);
    return *reinterpret_cast<uint32_t*>(&h);
}

// ---------------- Phase 1: L2-normalize rows -> bf16; zero g_density ----------------
__global__ void normalize_kernel(const float* __restrict__ x) {
    int gwarp = (blockIdx.x * blockDim.x + threadIdx.x) >> 5;
    int lane  = threadIdx.x & 31;
    if (gwarp >= NROWS) return;
    const float4* p = reinterpret_cast<const float4*>(x + (size_t)gwarp * DIM);
    float4 v0 = p[lane * 2 + 0];
    float4 v1 = p[lane * 2 + 1];
    float ss = v0.x*v0.x + v0.y*v0.y + v0.z*v0.z + v0.w*v0.w
             + v1.x*v1.x + v1.y*v1.y + v1.z*v1.z + v1.w*v1.w;
    #pragma unroll
    for (int o = 16; o; o >>= 1) ss += __shfl_xor_sync(0xffffffffu, ss, o);
    float inv = 1.0f / fmaxf(sqrtf(ss), 1e-12f);

    uint4 out;
    out.x = pack_bf2(v0.x * inv, v0.y * inv);
    out.y = pack_bf2(v0.z * inv, v0.w * inv);
    out.z = pack_bf2(v1.x * inv, v1.y * inv);
    out.w = pack_bf2(v1.z * inv, v1.w * inv);
    reinterpret_cast<uint4*>(g_xn)[gwarp * (DIM / 8) + lane] = out;
    if (lane == 0) g_density[gwarp] = 0.0f;
}

// ---------------- helpers ----------------
static __device__ __forceinline__ void ldsm_x4(uint32_t* r, uint32_t addr) {
    asm volatile("ldmatrix.sync.aligned.m8n8.x4.shared.b16 {%0,%1,%2,%3}, [%4];\n"
                 : "=r"(r[0]), "=r"(r[1]), "=r"(r[2]), "=r"(r[3]) : "r"(addr));
}
static __device__ __forceinline__ void mma_bf16(float* c, const uint32_t* a, const uint32_t* b) {
    asm volatile("mma.sync.aligned.m16n8k16.row.col.f32.bf16.bf16.f32 "
                 "{%0,%1,%2,%3}, {%4,%5,%6,%7}, {%8,%9}, {%0,%1,%2,%3};\n"
                 : "+f"(c[0]), "+f"(c[1]), "+f"(c[2]), "+f"(c[3])
                 : "r"(a[0]), "r"(a[1]), "r"(a[2]), "r"(a[3]),
                   "r"(b[0]), "r"(b[1]));
}
static __device__ __forceinline__ float fex2(float x) {
    float r; asm("ex2.approx.ftz.f32 %0, %1;" : "=f"(r) : "f"(x)); return r;
}
#define CP_ASYNC16(dst, src) \
    asm volatile("cp.async.cg.shared.global [%0], [%1], 16;" :: "r"(dst), "l"(src) : "memory")
#define CP_COMMIT()  asm volatile("cp.async.commit_group;" ::: "memory")
#define CP_WAIT0()   asm volatile("cp.async.wait_group 0;" :: : "memory")
#define CP_WAIT1()   asm volatile("cp.async.wait_group 1;" :: : "memory")
#define BAR_GROUP(id) \
    asm volatile("bar.sync %0, 128;" :: "r"(id) : "memory")

// A tile load: 128x512B padded rows (4096 x 16B, 8 per thread @512). No commit.
static __device__ __forceinline__ void load_tile_A(uint32_t dst_base, int grow0, int tid) {
    #pragma unroll
    for (int i = 0; i < 8; ++i) {
        int id = i * NTHR + tid;
        int r = id >> 5, u = id & 31;
        uint32_t dst = dst_base + (uint32_t)(r * LDSB + u * 16);
        const char* src = (const char*)g_xn + ((size_t)(grow0 + r) * DIM + u * 8) * 2;
        CP_ASYNC16(dst, src);
    }
}

// B k-half slice: 64 sim-cols (g_xn rows jrow0..+64), k-half kh, into buffer rows
// [64g, 64g+64) of Bh (256B swizzled rows). 128 threads x 8 x 16B. Commits.
static __device__ __forceinline__ void load_b_half(uint32_t Bh, int jrow0, int g,
                                                   int gt, int kh) {
    #pragma unroll
    for (int i = 0; i < 8; ++i) {
        int idx = i * 128 + gt;              // 0..1023
        int lr = idx >> 4;                   // 0..63
        int u  = idx & 15;                   // 16B unit in 256B row
        int br = g * 64 + lr;
        uint32_t dst = Bh + (uint32_t)(br * 256 + ((u ^ (br & 7)) << 4));
        const char* src = (const char*)g_xn + ((size_t)(jrow0 + lr) * DIM + kh * 128 + u * 8) * 2;
        CP_ASYNC16(dst, src);
    }
    CP_COMMIT();
}

// pair-ordered global tile index -> (ti, tj), ti <= tj
static __device__ __forceinline__ void tile_of(int q, int& ti, int& tj) {
    int p = q / 129, r = q - p * 129;
    int seg1 = NT - p;
    if (r < seg1) { ti = p;          tj = p + r; }
    else          { ti = NT - 1 - p; tj = NT - 1 - p + (r - seg1); }
}

// super-iteration parameters (group-uniform)
static __device__ __forceinline__ void super_params(int q, int qend, int ti, int tj,
                                                    int warp_n, bool& dbl, bool& active,
                                                    int& colbase, bool& diag) {
    dbl = false;
    if (q + 1 < qend) {
        int t2, j2;
        tile_of(q + 1, t2, j2);
        dbl = (t2 == ti) && (j2 == tj + 1);
    }
    active = dbl || (warp_n < 2);
    int tj_eff = (warp_n < 2) ? tj : tj + 1;
    colbase = tj_eff * 128 + (warp_n & 1) * 64;
    diag = (tj_eff == ti);
}

// frag load helpers
static __device__ __forceinline__ void load_fa(uint32_t fa[2][4], uint32_t Ab,
                                               int a_rb, int ks) {
    ldsm_x4(fa[0], Ab + (uint32_t)(a_rb + ks * 32));
    ldsm_x4(fa[1], Ab + (uint32_t)(16 * LDSB + a_rb + ks * 32));
}
static __device__ __forceinline__ void load_fb(uint32_t fb[8][2], uint32_t Bh_l,
                                               int xl, int ub0, int ksl) {
    uint32_t un = (uint32_t)(((2 * ksl + ub0) ^ xl) << 4);
    #pragma unroll
    for (int p = 0; p < 4; ++p) {
        uint32_t t[4];
        ldsm_x4(t, Bh_l + (uint32_t)(p * 4096) + un);
        fb[2*p][0]   = t[0]; fb[2*p][1]   = t[1];
        fb[2*p+1][0] = t[2]; fb[2*p+1][1] = t[3];
    }
}

// half mainloop: 8 ksteps of k16, frag ping-pong (prefetch ks+1 before ks MMAs)
template <bool FIRST>
static __device__ __forceinline__ void mainloop_half(
    uint32_t Ab, uint32_t Bh_l, int a_rb, int xl, int ub0, int ks0,
    float acc[2][8][4])
{
    if (FIRST) {
        #pragma unroll
        for (int mf = 0; mf < 2; ++mf)
            #pragma unroll
            for (int nf = 0; nf < 8; ++nf)
                #pragma unroll
                for (int e = 0; e < 4; ++e) acc[mf][nf][e] = 0.f;
    }

    uint32_t fa[2][2][4];   // [slot][mf][4]
    uint32_t fb[2][8][2];   // [slot][nf][2]
    load_fa(fa[0], Ab, a_rb, ks0);
    load_fb(fb[0], Bh_l, xl, ub0, 0);

    #pragma unroll
    for (int ksl = 0; ksl < 8; ++ksl) {
        int cur = ksl & 1, nxt = cur ^ 1;
        if (ksl < 7) {                        // prefetch next kstep under MMA issue
            load_fa(fa[nxt], Ab, a_rb, ks0 + ksl + 1);
            load_fb(fb[nxt], Bh_l, xl, ub0, ksl + 1);
        }
        #pragma unroll
        for (int mf = 0; mf < 2; ++mf)
            #pragma unroll
            for (int nf = 0; nf < 8; ++nf)
                mma_bf16(acc[mf][nf], fa[cur][mf], fb[cur][nf]);
    }
}

// epilogue: exp + row sums (regs) + col sums (shfl + atomics)
static __device__ __forceinline__ void epi_iter(
    float acc[2][8][4], float rowacc[2][2],
    int colbase, bool diag, int lane)
{
    #pragma unroll
    for (int nf = 0; nf < 8; ++nf) {
        float c0 = 0.f, c1 = 0.f;
        #pragma unroll
        for (int mf = 0; mf < 2; ++mf) {
            float e0 = fex2(KSL2 * acc[mf][nf][0]);
            float e1 = fex2(KSL2 * acc[mf][nf][1]);
            float e2 = fex2(KSL2 * acc[mf][nf][2]);
            float e3 = fex2(KSL2 * acc[mf][nf][3]);
            rowacc[mf][0] += e0 + e1;
            rowacc[mf][1] += e2 + e3;
            c0 += e0 + e2;
            c1 += e1 + e3;
        }
        if (!diag) {
            c0 += __shfl_xor_sync(0xffffffffu, c0, 4);
            c0 += __shfl_xor_sync(0xffffffffu, c0, 8);
            c0 += __shfl_xor_sync(0xffffffffu, c0, 16);
            c1 += __shfl_xor_sync(0xffffffffu, c1, 4);
            c1 += __shfl_xor_sync(0xffffffffu, c1, 8);
            c1 += __shfl_xor_sync(0xffffffffu, c1, 16);
            if (lane < 4) {
                atomicAdd(&g_density[colbase + nf * 8 + 2 * lane + 0], c0);
                atomicAdd(&g_density[colbase + nf * 8 + 2 * lane + 1], c1);
            }
        }
    }
}

static __device__ __forceinline__ void flush_rows(float rowacc[2][2], int ti,
                                                  int warp_m, int lane) {
    #pragma unroll
    for (int mf = 0; mf < 2; ++mf)
        #pragma unroll
        for (int rp = 0; rp < 2; ++rp) {
            float s = rowacc[mf][rp];
            s += __shfl_xor_sync(0xffffffffu, s, 1);
            s += __shfl_xor_sync(0xffffffffu, s, 2);
            if ((lane & 3) == 0)
                atomicAdd(&g_density[ti * 128 + warp_m * 32 + mf * 16 + rp * 8 + (lane >> 2)], s);
            rowacc[mf][rp] = 0.f;
        }
}

// ---------------- Phase 2: persistent BF16 symmetric GEMM, k-half pipelined ----------
__global__ void __launch_bounds__(NTHR, 1) kde_sym_kernel() {
    extern __shared__ uint8_t sm[];
    uint32_t A_sm = (uint32_t)__cvta_generic_to_shared(sm);
    uint32_t B0_sm = A_sm + A_BYTES;
    uint32_t B1_sm = B0_sm + BH_BYTES;

    int tid  = threadIdx.x;
    int lane = tid & 31;
    int wid  = tid >> 5;
    int warp_m = wid & 3;        // 4 warps in M: 32 rows each (SMSP = warp_m)
    int warp_n = wid >> 2;       // 4 groups in N: 64 sim-cols each
    int gt   = tid & 127;
    int bar_id = warp_n + 1;

    int qbeg = (int)(((long long)blockIdx.x * NTILES) / NCTA);
    int qend = (int)(((long long)(blockIdx.x + 1) * NTILES) / NCTA);

    int a_rb = (lane & 15) * LDSB + ((lane >> 4) * 16);
    uint32_t Ab = A_sm + (uint32_t)(warp_m * 32 * LDSB);
    uint32_t b_lrow = (uint32_t)(warp_n * 16384 +
                      ((lane & 7) + ((lane >> 4) << 3)) * 256);
    uint32_t B0_l = B0_sm + b_lrow;
    uint32_t B1_l = B1_sm + b_lrow;
    int xl  = lane & 7;
    int ub0 = (lane >> 3) & 1;

    int ti, tj;
    tile_of(qbeg, ti, tj);
    int cur_ti = ti;

    // prologue: A panel + B0(qbeg) k-half
    {
        bool dbl0, active0; int colbase0; bool diag0;
        super_params(qbeg, qend, ti, tj, warp_n, dbl0, active0, colbase0, diag0);
        load_tile_A(A_sm, ti * 128, tid);
        if (active0) load_b_half(B0_sm, colbase0, warp_n, gt, 0);   // commits A+B0
        else         CP_COMMIT();
        CP_WAIT0();
        __syncthreads();
    }

    float rowacc[2][2] = {{0.f,0.f},{0.f,0.f}};
    float acc[2][8][4];
    bool have_prev = false, prev_active = false, prev_diag = false;
    int prev_colbase = 0;

    int q = qbeg;
    while (q < qend) {
        tile_of(q, ti, tj);
        bool dbl, active; int colbase; bool diag;
        super_params(q, qend, ti, tj, warp_n, dbl, active, colbase, diag);

        if (ti != cur_ti) {                    // A-panel switch (<=2 per CTA): full drain
            if (have_prev) {
                if (prev_active) epi_iter(acc, rowacc, prev_colbase, prev_diag, lane);
                have_prev = false;
            }
            flush_rows(rowacc, cur_ti, warp_m, lane);
            CP_WAIT0();                        // drain B0(q) prefetch
            __syncthreads();
            load_tile_A(A_sm, ti * 128, tid);
            CP_COMMIT(); CP_WAIT0();
            __syncthreads();
            cur_ti = ti;
        }

        // ---- phase 1: issue B1(q); epi(prev) under load latency; compute on B0(q) ----
        BAR_GROUP(bar_id);                     // group done reading B1(q-1)
        if (active) load_b_half(B1_sm, colbase, warp_n, gt, 1);
        else        CP_COMMIT();
        if (have_prev && prev_active)
            epi_iter(acc, rowacc, prev_colbase, prev_diag, lane);
        CP_WAIT1();                            // B0(q) done (B1(q) may be in flight)
        BAR_GROUP(bar_id);                     // B0(q) visible group-wide
        if (active) mainloop_half<true>(Ab, B0_l, a_rb, xl, ub0, 0, acc);

        // ---- phase 2: prefetch B0(next); compute on B1(q) ----
        int qn = q + (dbl ? 2 : 1);
        BAR_GROUP(bar_id);                     // group done reading B0(q)
        if (qn < qend) {
            int ti_n, tj_n;
            tile_of(qn, ti_n, tj_n);
            bool dbl_n, active_n; int colbase_n; bool diag_n;
            super_params(qn, qend, ti_n, tj_n, warp_n, dbl_n, active_n, colbase_n, diag_n);
            if (active_n) load_b_half(B0_sm, colbase_n, warp_n, gt, 0);
            else          CP_COMMIT();
        } else CP_COMMIT();
        CP_WAIT1();                            // B1(q) done (B0(next) may be in flight)
        BAR_GROUP(bar_id);                     // B1(q) visible group-wide
        if (active) mainloop_half<false>(Ab, B1_l, a_rb, xl, ub0, 8, acc);

        have_prev = true;
        prev_active = active;
        prev_colbase = colbase;
        prev_diag = diag;
        q = qn;
    }

    // drain
    if (have_prev && prev_active)
        epi_iter(acc, rowacc, prev_colbase, prev_diag, lane);
    flush_rows(rowacc, cur_ti, warp_m, lane);
}

// ---------------- Phase 3: entropy = -mean(log(density + 1e-9)) ----------------
__global__ void entropy_kernel(float* __restrict__ out) {
    __shared__ float red[1024];
    int t = threadIdx.x;
    float s = 0.f;
    for (int i = t; i < NROWS; i += 1024)
        s += logf(g_density[i] + 1e-9f);
    red[t] = s;
    __syncthreads();
    #pragma unroll
    for (int o = 512; o; o >>= 1) {
        if (t < o) red[t] += red[t + o];
        __syncthreads();
    }
    if (t == 0) out[0] = -red[0] / (float)NROWS;
}

__global__ void dummy_kernel() {}   // padding: keeps GEMM in ncu's capture slot (pos 3)

// ---------------- launch ----------------
extern "C" void kernel_launch(void* const* d_in, const int* in_sizes, int n_in,
                              void* d_out, int out_size) {
    (void)in_sizes; (void)n_in; (void)out_size;
    const float* x = (const float*)d_in[0];
    float* out = (float*)d_out;

    cudaFuncSetAttribute(kde_sym_kernel,
                         cudaFuncAttributeMaxDynamicSharedMemorySize, SMEM_BYTES);

    normalize_kernel<<<NROWS / 8, 256>>>(x);       // pos 0
    dummy_kernel<<<1, 32>>>();                     // pos 1
    dummy_kernel<<<1, 32>>>();                     // pos 2
    kde_sym_kernel<<<NCTA, NTHR, SMEM_BYTES>>>();  // pos 3 <- ncu capture slot
    entropy_kernel<<<1, 1024>>>(out);              // pos 4
}

// round 17
// speedup vs baseline: 1.4536x; 1.4536x over previous
#include <cuda_runtime.h>
#include <cuda_bf16.h>
#include <cstdint>

#define NROWS 16384
#define DIM   256
#define NT    128
#define NTILES 8256                // NT*(NT+1)/2
#define NCTA  148
#define NTHR  512
#define LDSB  528                  // A: bytes per smem row (512 + 16 pad)
#define KSL2  (5.0f * 1.44269504088896f)        // kappa * log2e
#define A_BYTES  (128 * LDSB)                   // 67584
#define BH_BYTES (256 * 256)                    // 65536 per k-half buffer
#define SMEM_BYTES (A_BYTES + 2 * BH_BYTES)     // 198656

__device__ __nv_bfloat16 g_xn[NROWS * DIM];   // normalized rows, bf16
__device__ float         g_density[NROWS];
__device__ unsigned int  g_ticket;

static __device__ __forceinline__ uint32_t pack_bf2(float a, float b) {
    __nv_bfloat162 h = __floats2bfloat162_rn(a, b);
    return *reinterpret_cast<uint32_t*>(&h);
}

// ---------------- Phase 1: L2-normalize rows -> bf16; zero g_density; reset ticket -------
__global__ void normalize_kernel(const float* __restrict__ x) {
    if (blockIdx.x == 0 && threadIdx.x == 0) g_ticket = 0u;   // graph-replay safe reset
    int gwarp = (blockIdx.x * blockDim.x + threadIdx.x) >> 5;
    int lane  = threadIdx.x & 31;
    if (gwarp >= NROWS) return;
    const float4* p = reinterpret_cast<const float4*>(x + (size_t)gwarp * DIM);
    float4 v0 = p[lane * 2 + 0];
    float4 v1 = p[lane * 2 + 1];
    float ss = v0.x*v0.x + v0.y*v0.y + v0.z*v0.z + v0.w*v0.w
             + v1.x*v1.x + v1.y*v1.y + v1.z*v1.z + v1.w*v1.w;
    #pragma unroll
    for (int o = 16; o; o >>= 1) ss += __shfl_xor_sync(0xffffffffu, ss, o);
    float inv = 1.0f / fmaxf(sqrtf(ss), 1e-12f);

    uint4 out;
    out.x = pack_bf2(v0.x * inv, v0.y * inv);
    out.y = pack_bf2(v0.z * inv, v0.w * inv);
    out.z = pack_bf2(v1.x * inv, v1.y * inv);
    out.w = pack_bf2(v1.z * inv, v1.w * inv);
    reinterpret_cast<uint4*>(g_xn)[gwarp * (DIM / 8) + lane] = out;
    if (lane == 0) g_density[gwarp] = 0.0f;
}

// ---------------- helpers ----------------
static __device__ __forceinline__ void ldsm_x4(uint32_t* r, uint32_t addr) {
    asm volatile("ldmatrix.sync.aligned.m8n8.x4.shared.b16 {%0,%1,%2,%3}, [%4];\n"
                 : "=r"(r[0]), "=r"(r[1]), "=r"(r[2]), "=r"(r[3]) : "r"(addr));
}
static __device__ __forceinline__ void mma_bf16(float* c, const uint32_t* a, const uint32_t* b) {
    asm volatile("mma.sync.aligned.m16n8k16.row.col.f32.bf16.bf16.f32 "
                 "{%0,%1,%2,%3}, {%4,%5,%6,%7}, {%8,%9}, {%0,%1,%2,%3};\n"
                 : "+f"(c[0]), "+f"(c[1]), "+f"(c[2]), "+f"(c[3])
                 : "r"(a[0]), "r"(a[1]), "r"(a[2]), "r"(a[3]),
                   "r"(b[0]), "r"(b[1]));
}
static __device__ __forceinline__ float fex2(float x) {
    float r; asm("ex2.approx.ftz.f32 %0, %1;" : "=f"(r) : "f"(x)); return r;
}
#define CP_ASYNC16(dst, src) \
    asm volatile("cp.async.cg.shared.global [%0], [%1], 16;" :: "r"(dst), "l"(src) : "memory")
#define CP_COMMIT()  asm volatile("cp.async.commit_group;" ::: "memory")
#define CP_WAIT0()   asm volatile("cp.async.wait_group 0;" :: : "memory")
#define CP_WAIT1()   asm volatile("cp.async.wait_group 1;" :: : "memory")
#define BAR_GROUP(id) \
    asm volatile("bar.sync %0, 128;" :: "r"(id) : "memory")

// A tile load: 128x512B padded rows (4096 x 16B, 8 per thread @512). No commit.
static __device__ __forceinline__ void load_tile_A(uint32_t dst_base, int grow0, int tid) {
    #pragma unroll
    for (int i = 0; i < 8; ++i) {
        int id = i * NTHR + tid;
        int r = id >> 5, u = id & 31;
        uint32_t dst = dst_base + (uint32_t)(r * LDSB + u * 16);
        const char* src = (const char*)g_xn + ((size_t)(grow0 + r) * DIM + u * 8) * 2;
        CP_ASYNC16(dst, src);
    }
}

// B k-half slice: 64 sim-cols (g_xn rows jrow0..+64), k-half kh, into buffer rows
// [64g, 64g+64) of Bh (256B swizzled rows). 128 threads x 8 x 16B. Commits.
static __device__ __forceinline__ void load_b_half(uint32_t Bh, int jrow0, int g,
                                                   int gt, int kh) {
    #pragma unroll
    for (int i = 0; i < 8; ++i) {
        int idx = i * 128 + gt;              // 0..1023
        int lr = idx >> 4;                   // 0..63
        int u  = idx & 15;                   // 16B unit in 256B row
        int br = g * 64 + lr;
        uint32_t dst = Bh + (uint32_t)(br * 256 + ((u ^ (br & 7)) << 4));
        const char* src = (const char*)g_xn + ((size_t)(jrow0 + lr) * DIM + kh * 128 + u * 8) * 2;
        CP_ASYNC16(dst, src);
    }
    CP_COMMIT();
}

// pair-ordered global tile index -> (ti, tj), ti <= tj
static __device__ __forceinline__ void tile_of(int q, int& ti, int& tj) {
    int p = q / 129, r = q - p * 129;
    int seg1 = NT - p;
    if (r < seg1) { ti = p;          tj = p + r; }
    else          { ti = NT - 1 - p; tj = NT - 1 - p + (r - seg1); }
}

// super-iteration parameters (group-uniform)
static __device__ __forceinline__ void super_params(int q, int qend, int ti, int tj,
                                                    int warp_n, bool& dbl, bool& active,
                                                    int& colbase, bool& diag) {
    dbl = false;
    if (q + 1 < qend) {
        int t2, j2;
        tile_of(q + 1, t2, j2);
        dbl = (t2 == ti) && (j2 == tj + 1);
    }
    active = dbl || (warp_n < 2);
    int tj_eff = (warp_n < 2) ? tj : tj + 1;
    colbase = tj_eff * 128 + (warp_n & 1) * 64;
    diag = (tj_eff == ti);
}

// half mainloop: 8 ksteps of k16 on one k-half buffer; 16 MMAs per kstep
template <bool FIRST>
static __device__ __forceinline__ void mainloop_half(
    uint32_t Ab, uint32_t Bh_l, int a_rb, int xl, int ub0, int ks0,
    float acc[2][8][4])
{
    if (FIRST) {
        #pragma unroll
        for (int mf = 0; mf < 2; ++mf)
            #pragma unroll
            for (int nf = 0; nf < 8; ++nf)
                #pragma unroll
                for (int e = 0; e < 4; ++e) acc[mf][nf][e] = 0.f;
    }
    #pragma unroll
    for (int ksl = 0; ksl < 8; ++ksl) {
        uint32_t fa[2][4];
        ldsm_x4(fa[0], Ab + (uint32_t)(a_rb + (ks0 + ksl) * 32));
        ldsm_x4(fa[1], Ab + (uint32_t)(16 * LDSB + a_rb + (ks0 + ksl) * 32));
        uint32_t un = (uint32_t)(((2 * ksl + ub0) ^ xl) << 4);
        uint32_t fb[8][2];
        #pragma unroll
        for (int p = 0; p < 4; ++p) {
            uint32_t t[4];
            ldsm_x4(t, Bh_l + (uint32_t)(p * 4096) + un);
            fb[2*p][0]   = t[0]; fb[2*p][1]   = t[1];
            fb[2*p+1][0] = t[2]; fb[2*p+1][1] = t[3];
        }
        #pragma unroll
        for (int mf = 0; mf < 2; ++mf)
            #pragma unroll
            for (int nf = 0; nf < 8; ++nf)
                mma_bf16(acc[mf][nf], fa[mf], fb[nf]);
    }
}

// epilogue: exp + row sums (regs) + col sums (shfl + atomics)
static __device__ __forceinline__ void epi_iter(
    float acc[2][8][4], float rowacc[2][2],
    int colbase, bool diag, int lane)
{
    #pragma unroll
    for (int nf = 0; nf < 8; ++nf) {
        float c0 = 0.f, c1 = 0.f;
        #pragma unroll
        for (int mf = 0; mf < 2; ++mf) {
            float e0 = fex2(KSL2 * acc[mf][nf][0]);
            float e1 = fex2(KSL2 * acc[mf][nf][1]);
            float e2 = fex2(KSL2 * acc[mf][nf][2]);
            float e3 = fex2(KSL2 * acc[mf][nf][3]);
            rowacc[mf][0] += e0 + e1;
            rowacc[mf][1] += e2 + e3;
            c0 += e0 + e2;
            c1 += e1 + e3;
        }
        if (!diag) {
            c0 += __shfl_xor_sync(0xffffffffu, c0, 4);
            c0 += __shfl_xor_sync(0xffffffffu, c0, 8);
            c0 += __shfl_xor_sync(0xffffffffu, c0, 16);
            c1 += __shfl_xor_sync(0xffffffffu, c1, 4);
            c1 += __shfl_xor_sync(0xffffffffu, c1, 8);
            c1 += __shfl_xor_sync(0xffffffffu, c1, 16);
            if (lane < 4) {
                atomicAdd(&g_density[colbase + nf * 8 + 2 * lane + 0], c0);
                atomicAdd(&g_density[colbase + nf * 8 + 2 * lane + 1], c1);
            }
        }
    }
}

static __device__ __forceinline__ void flush_rows(float rowacc[2][2], int ti,
                                                  int warp_m, int lane) {
    #pragma unroll
    for (int mf = 0; mf < 2; ++mf)
        #pragma unroll
        for (int rp = 0; rp < 2; ++rp) {
            float s = rowacc[mf][rp];
            s += __shfl_xor_sync(0xffffffffu, s, 1);
            s += __shfl_xor_sync(0xffffffffu, s, 2);
            if ((lane & 3) == 0)
                atomicAdd(&g_density[ti * 128 + warp_m * 32 + mf * 16 + rp * 8 + (lane >> 2)], s);
            rowacc[mf][rp] = 0.f;
        }
}

// ---------------- Phase 2: persistent BF16 symmetric GEMM, k-half pipelined,
//                  fused entropy tail (last CTA reduces) ----------
__global__ void __launch_bounds__(NTHR, 1) kde_sym_kernel(float* __restrict__ out) {
    extern __shared__ uint8_t sm[];
    uint32_t A_sm = (uint32_t)__cvta_generic_to_shared(sm);
    uint32_t B0_sm = A_sm + A_BYTES;
    uint32_t B1_sm = B0_sm + BH_BYTES;

    int tid  = threadIdx.x;
    int lane = tid & 31;
    int wid  = tid >> 5;
    int warp_m = wid & 3;        // 4 warps in M: 32 rows each (SMSP = warp_m)
    int warp_n = wid >> 2;       // 4 groups in N: 64 sim-cols each
    int gt   = tid & 127;
    int bar_id = warp_n + 1;

    int qbeg = (int)(((long long)blockIdx.x * NTILES) / NCTA);
    int qend = (int)(((long long)(blockIdx.x + 1) * NTILES) / NCTA);

    int a_rb = (lane & 15) * LDSB + ((lane >> 4) * 16);
    uint32_t Ab = A_sm + (uint32_t)(warp_m * 32 * LDSB);
    uint32_t b_lrow = (uint32_t)(warp_n * 16384 +
                      ((lane & 7) + ((lane >> 4) << 3)) * 256);
    uint32_t B0_l = B0_sm + b_lrow;
    uint32_t B1_l = B1_sm + b_lrow;
    int xl  = lane & 7;
    int ub0 = (lane >> 3) & 1;

    int ti, tj;
    tile_of(qbeg, ti, tj);
    int cur_ti = ti;

    // prologue: A panel + B0(qbeg) k-half
    {
        bool dbl0, active0; int colbase0; bool diag0;
        super_params(qbeg, qend, ti, tj, warp_n, dbl0, active0, colbase0, diag0);
        load_tile_A(A_sm, ti * 128, tid);
        if (active0) load_b_half(B0_sm, colbase0, warp_n, gt, 0);   // commits A+B0
        else         CP_COMMIT();
        CP_WAIT0();
        __syncthreads();
    }

    float rowacc[2][2] = {{0.f,0.f},{0.f,0.f}};
    float acc[2][8][4];
    bool have_prev = false, prev_active = false, prev_diag = false;
    int prev_colbase = 0;

    int q = qbeg;
    while (q < qend) {
        tile_of(q, ti, tj);
        bool dbl, active; int colbase; bool diag;
        super_params(q, qend, ti, tj, warp_n, dbl, active, colbase, diag);

        if (ti != cur_ti) {                    // A-panel switch (<=2 per CTA): full drain
            if (have_prev) {
                if (prev_active) epi_iter(acc, rowacc, prev_colbase, prev_diag, lane);
                have_prev = false;
            }
            flush_rows(rowacc, cur_ti, warp_m, lane);
            CP_WAIT0();                        // drain B0(q) prefetch
            __syncthreads();
            load_tile_A(A_sm, ti * 128, tid);
            CP_COMMIT(); CP_WAIT0();
            __syncthreads();
            cur_ti = ti;
        }

        // ---- phase 1: issue B1(q); epi(prev) under load latency; compute on B0(q) ----
        BAR_GROUP(bar_id);                     // group done reading B1(q-1)
        if (active) load_b_half(B1_sm, colbase, warp_n, gt, 1);
        else        CP_COMMIT();
        if (have_prev && prev_active)
            epi_iter(acc, rowacc, prev_colbase, prev_diag, lane);
        CP_WAIT1();                            // B0(q) done (B1(q) may be in flight)
        BAR_GROUP(bar_id);                     // B0(q) visible group-wide
        if (active) mainloop_half<true>(Ab, B0_l, a_rb, xl, ub0, 0, acc);

        // ---- phase 2: prefetch B0(next); compute on B1(q) ----
        int qn = q + (dbl ? 2 : 1);
        BAR_GROUP(bar_id);                     // group done reading B0(q)
        if (qn < qend) {
            int ti_n, tj_n;
            tile_of(qn, ti_n, tj_n);
            bool dbl_n, active_n; int colbase_n; bool diag_n;
            super_params(qn, qend, ti_n, tj_n, warp_n, dbl_n, active_n, colbase_n, diag_n);
            if (active_n) load_b_half(B0_sm, colbase_n, warp_n, gt, 0);
            else          CP_COMMIT();
        } else CP_COMMIT();
        CP_WAIT1();                            // B1(q) done (B0(next) may be in flight)
        BAR_GROUP(bar_id);                     // B1(q) visible group-wide
        if (active) mainloop_half<false>(Ab, B1_l, a_rb, xl, ub0, 8, acc);

        have_prev = true;
        prev_active = active;
        prev_colbase = colbase;
        prev_diag = diag;
        q = qn;
    }

    // drain
    if (have_prev && prev_active)
        epi_iter(acc, rowacc, prev_colbase, prev_diag, lane);
    flush_rows(rowacc, cur_ti, warp_m, lane);

    // ---- fused entropy tail: last CTA to finish reduces g_density -> out[0] ----
    __threadfence();                           // my atomics visible before ticket bump
    __shared__ unsigned int my_ticket;
    __syncthreads();                           // all warps' atomics issued before fence? (fence
                                               // per-thread; each thread fenced its own writes)
    if (tid == 0) my_ticket = atomicAdd(&g_ticket, 1u);
    __syncthreads();
    if (my_ticket == NCTA - 1) {
        float s = 0.f;
        for (int i = tid; i < NROWS; i += NTHR) {
            float d = __ldcg(&g_density[i]);   // bypass L1: values live in L2 (atomics)
            s += __logf(d + 1e-9f);
        }
        #pragma unroll
        for (int o = 16; o; o >>= 1) s += __shfl_xor_sync(0xffffffffu, s, o);
        float* red = (float*)sm;
        if (lane == 0) red[wid] = s;
        __syncthreads();
        if (tid < 16) {
            float v = red[tid];
            #pragma unroll
            for (int o = 8; o; o >>= 1) v += __shfl_xor_sync(0xffffu, v, o);
            if (tid == 0) out[0] = -v / (float)NROWS;
        }
    }
}

// ---------------- launch ----------------
extern "C" void kernel_launch(void* const* d_in, const int* in_sizes, int n_in,
                              void* d_out, int out_size) {
    (void)in_sizes; (void)n_in; (void)out_size;
    const float* x = (const float*)d_in[0];
    float* out = (float*)d_out;

    cudaFuncSetAttribute(kde_sym_kernel,
                         cudaFuncAttributeMaxDynamicSharedMemorySize, SMEM_BYTES);

    normalize_kernel<<<NROWS / 8, 256>>>(x);
    kde_sym_kernel<<<NCTA, NTHR, SMEM_BYTES>>>(out);
}